// round 1
// baseline (speedup 1.0000x reference)
#include <cuda_runtime.h>
#include <cstdint>

#define NMAX   100000
#define EMAX   1600000
#define NFEAT  256
#define NHID   64
#define NEG_SLOPE 0.2f

// ---------------- scratch (device globals: alloc-free, graph-capturable) ----
__device__ float g_xp[(size_t)NMAX * NHID];      // transformed features  25.6 MB
__device__ float g_ssrc[NMAX];                   // xp . a_src
__device__ float g_sdst[NMAX];                   // xp . a_dst
__device__ float g_m[NMAX];                      // segment max
__device__ float g_denom[NMAX];                  // segment sum of exp
__device__ float g_ex[EMAX + NMAX];              // per-edge exp(e - m)
__device__ int   g_is64;                         // edge_index dtype flag

// ---------------- dtype sniffing ------------------------------------------
// int64 little-endian with values < 2^31  =>  every odd 32-bit word is 0.
// int32 random edge ids  =>  odd words are random in [0,N); all-zero is ~impossible.
__global__ void detect_kernel(const unsigned int* __restrict__ w) {
    __shared__ int any;
    if (threadIdx.x == 0) any = 0;
    __syncthreads();
    int found = 0;
    for (int i = 1 + 2 * threadIdx.x; i < 4096; i += 2 * blockDim.x)
        if (w[i] != 0u) found = 1;
    if (found) atomicExch(&any, 1);
    __syncthreads();
    if (threadIdx.x == 0) g_is64 = (any == 0) ? 1 : 0;
}

__device__ __forceinline__ void load_edge(const void* ei, int i, int E,
                                          int is64, int& s, int& d) {
    if (i < E) {
        if (is64) {
            const long long* p = (const long long*)ei;
            s = (int)p[i]; d = (int)p[E + i];
        } else {
            const int* p = (const int*)ei;
            s = p[i]; d = p[E + i];
        }
    } else {
        s = d = i - E;   // self loop
    }
}

// ---------------- GEMM: xp = x @ W  (fp32 SIMT, shared-tiled) --------------
// Block: 256 threads, 64 rows/block. W (256x64) fully staged in smem,
// x tile (64x256) staged with pad 260 (bank-clean, float4-aligned).
#define XPAD 260
__global__ void __launch_bounds__(256, 1)
gemm_kernel(const float* __restrict__ x, const float* __restrict__ W, int Nn) {
    extern __shared__ float sm[];
    float* Ws = sm;                       // 256*64
    float* xs = sm + NFEAT * NHID;        // 64*XPAD
    const int tid  = threadIdx.x;
    const int row0 = blockIdx.x * 64;

    #pragma unroll
    for (int i = tid; i < NFEAT * NHID / 4; i += 256)
        ((float4*)Ws)[i] = ((const float4*)W)[i];

    for (int i = tid; i < 64 * (NFEAT / 4); i += 256) {
        int r  = i / (NFEAT / 4);
        int k4 = i % (NFEAT / 4);
        float4 v = make_float4(0.f, 0.f, 0.f, 0.f);
        int row = row0 + r;
        if (row < Nn)
            v = ((const float4*)(x + (size_t)row * NFEAT))[k4];
        *(float4*)(xs + r * XPAD + k4 * 4) = v;
    }
    __syncthreads();

    const int tx = tid & 15, ty = tid >> 4;
    const int c0 = tx * 4, r0 = ty * 4;
    float acc[4][4];
    #pragma unroll
    for (int r = 0; r < 4; r++)
        #pragma unroll
        for (int c = 0; c < 4; c++) acc[r][c] = 0.f;

    const float* xr0 = xs + r0 * XPAD;
    #pragma unroll 4
    for (int k = 0; k < NFEAT; k++) {
        float4 b = *(const float4*)(Ws + k * NHID + c0);
        #pragma unroll
        for (int r = 0; r < 4; r++) {
            float a = xr0[r * XPAD + k];
            acc[r][0] += a * b.x; acc[r][1] += a * b.y;
            acc[r][2] += a * b.z; acc[r][3] += a * b.w;
        }
    }

    #pragma unroll
    for (int r = 0; r < 4; r++) {
        int row = row0 + r0 + r;
        if (row < Nn)
            *(float4*)(g_xp + (size_t)row * NHID + c0) =
                make_float4(acc[r][0], acc[r][1], acc[r][2], acc[r][3]);
    }
}

// ---------------- s vectors + init (warp per node) -------------------------
__global__ void sinit_kernel(const float* __restrict__ a_src,
                             const float* __restrict__ a_dst,
                             const float* __restrict__ bias,
                             float* __restrict__ out, int Nn) {
    int node = (blockIdx.x * blockDim.x + threadIdx.x) >> 5;
    int lane = threadIdx.x & 31;
    if (node >= Nn) return;
    const float* row = g_xp + (size_t)node * NHID;
    float x0 = row[lane], x1 = row[lane + 32];
    float ss = x0 * a_src[lane] + x1 * a_src[lane + 32];
    float sd = x0 * a_dst[lane] + x1 * a_dst[lane + 32];
    #pragma unroll
    for (int o = 16; o > 0; o >>= 1) {
        ss += __shfl_down_sync(0xffffffffu, ss, o);
        sd += __shfl_down_sync(0xffffffffu, sd, o);
    }
    if (lane == 0) {
        g_ssrc[node]  = ss;
        g_sdst[node]  = sd;
        g_m[node]     = __int_as_float(0xff800000); // -inf
        g_denom[node] = 0.f;
    }
    out[(size_t)node * NHID + lane]      = bias[lane];
    out[(size_t)node * NHID + lane + 32] = bias[lane + 32];
}

// ---------------- float atomic max ------------------------------------------
__device__ __forceinline__ void atomicMaxF(float* addr, float v) {
    if (v >= 0.f) atomicMax((int*)addr, __float_as_int(v));
    else          atomicMin((unsigned int*)addr, __float_as_uint(v));
}

// ---------------- pass A: segment max ---------------------------------------
__global__ void edge_max_kernel(const void* __restrict__ ei, int E, int Nn) {
    int i = blockIdx.x * blockDim.x + threadIdx.x;
    if (i >= E + Nn) return;
    int is64 = g_is64;
    int s, d;
    load_edge(ei, i, E, is64, s, d);
    float e = g_ssrc[s] + g_sdst[d];
    e = e > 0.f ? e : NEG_SLOPE * e;
    atomicMaxF(&g_m[d], e);
}

// ---------------- pass B: exp + segment sum ----------------------------------
__global__ void edge_sum_kernel(const void* __restrict__ ei, int E, int Nn) {
    int i = blockIdx.x * blockDim.x + threadIdx.x;
    if (i >= E + Nn) return;
    int is64 = g_is64;
    int s, d;
    load_edge(ei, i, E, is64, s, d);
    float e = g_ssrc[s] + g_sdst[d];
    e = e > 0.f ? e : NEG_SLOPE * e;
    float ex = __expf(e - g_m[d]);
    g_ex[i] = ex;
    atomicAdd(&g_denom[d], ex);
}

// ---------------- pass C: normalize + weighted scatter (16 lanes/edge) -------
__global__ void scatter_kernel(const void* __restrict__ ei,
                               float* __restrict__ out, int E, int Nn) {
    int t    = blockIdx.x * blockDim.x + threadIdx.x;
    int i    = t >> 4;
    int lane = t & 15;
    if (i >= E + Nn) return;
    int is64 = g_is64;
    int s, d;
    load_edge(ei, i, E, is64, s, d);
    float alpha = __fdividef(g_ex[i], g_denom[d]);
    float4 v = ((const float4*)(g_xp + (size_t)s * NHID))[lane];
    v.x *= alpha; v.y *= alpha; v.z *= alpha; v.w *= alpha;
    float* o = out + (size_t)d * NHID + lane * 4;
    asm volatile("red.global.add.v4.f32 [%0], {%1,%2,%3,%4};"
                 :: "l"(o), "f"(v.x), "f"(v.y), "f"(v.z), "f"(v.w)
                 : "memory");
}

// ---------------- launch -----------------------------------------------------
extern "C" void kernel_launch(void* const* d_in, const int* in_sizes, int n_in,
                              void* d_out, int out_size) {
    const float* x     = (const float*)d_in[0];
    const void*  ei    = d_in[1];
    const float* W     = (const float*)d_in[2];
    const float* a_src = (const float*)d_in[3];
    const float* a_dst = (const float*)d_in[4];
    const float* bias  = (const float*)d_in[5];
    float* out = (float*)d_out;

    const int Nn = in_sizes[0] / NFEAT;
    const int E  = in_sizes[1] / 2;
    const int T  = E + Nn;

    const int smem = (NFEAT * NHID + 64 * XPAD) * (int)sizeof(float); // 132096 B
    cudaFuncSetAttribute(gemm_kernel,
                         cudaFuncAttributeMaxDynamicSharedMemorySize, smem);

    detect_kernel<<<1, 256>>>((const unsigned int*)ei);
    gemm_kernel<<<(Nn + 63) / 64, 256, smem>>>(x, W, Nn);
    sinit_kernel<<<(Nn + 7) / 8, 256>>>(a_src, a_dst, bias, out, Nn);
    edge_max_kernel<<<(T + 255) / 256, 256>>>(ei, E, Nn);
    edge_sum_kernel<<<(T + 255) / 256, 256>>>(ei, E, Nn);
    scatter_kernel<<<((T * 16) + 255) / 256, 256>>>(ei, out, E, Nn);
}